// round 1
// baseline (speedup 1.0000x reference)
#include <cuda_runtime.h>
#include <math_constants.h>

// Problem constants (fixed by setup_inputs)
#define N_    256
#define D_    512
#define Q_    2048
#define C_    1000
#define IMG_  150528   // 3*224*224
#define K_    4

// Output layout: labels | probs | images | grads (return order, float32)
#define OFF_LABELS 0
#define OFF_PROBS  (N_)
#define OFF_IMG    (N_ + N_*C_)
#define OFF_GRADS  (N_ + N_*C_ + N_*IMG_)

// Scratch (no cudaMalloc allowed)
__device__ float g_feat_inv[N_];
__device__ float g_bank_inv[Q_];
__device__ float g_dist[N_ * Q_];
__device__ int   g_topk[N_ * K_];

// ---------------------------------------------------------------------------
// Kernel A: inverse L2 norms for feature rows and bank rows.
// One block per row, 128 threads, each thread loads one float4 (512 floats).
// ---------------------------------------------------------------------------
__global__ void norms_kernel(const float* __restrict__ feats,
                             const float* __restrict__ bank) {
    int r = blockIdx.x;
    const float* src = (r < N_) ? (feats + (size_t)r * D_)
                                : (bank + (size_t)(r - N_) * D_);
    float4 v = reinterpret_cast<const float4*>(src)[threadIdx.x];
    float ss = v.x * v.x + v.y * v.y + v.z * v.z + v.w * v.w;
    #pragma unroll
    for (int o = 16; o > 0; o >>= 1)
        ss += __shfl_xor_sync(0xffffffffu, ss, o);
    __shared__ float ws[4];
    if ((threadIdx.x & 31) == 0) ws[threadIdx.x >> 5] = ss;
    __syncthreads();
    if (threadIdx.x == 0) {
        float s = ws[0] + ws[1] + ws[2] + ws[3];
        float inv = 1.0f / fmaxf(sqrtf(s), 1e-12f);
        if (r < N_) g_feat_inv[r] = inv;
        else        g_bank_inv[r - N_] = inv;
    }
}

// ---------------------------------------------------------------------------
// Kernel B: distance matrix, tiled to limit L2 re-reads of the bank.
// Grid (8, 32): blockIdx.x = q-chunk (256 candidates), blockIdx.y = group of
// 8 feature rows. 256 threads: each thread owns one candidate q and computes
// dots against all 8 feature rows held (pre-normalized) in shared memory.
// Bank L2 traffic: 8x redundancy = 128 MB total.
// ---------------------------------------------------------------------------
__global__ void dist_kernel(const float* __restrict__ feats,
                            const float* __restrict__ bank) {
    __shared__ float4 s_feat[8 * 128];   // 8 rows x 512 floats (16 KB)
    const int tid = threadIdx.x;
    const int r0  = blockIdx.y * 8;
    const int q   = blockIdx.x * 256 + tid;

    // Load 8 feature rows, pre-scaled by their inverse norms.
    for (int i = tid; i < 8 * 128; i += 256) {
        int rr = i >> 7, cc = i & 127;
        float4 v = reinterpret_cast<const float4*>(feats + (size_t)(r0 + rr) * D_)[cc];
        float inv = g_feat_inv[r0 + rr];
        v.x *= inv; v.y *= inv; v.z *= inv; v.w *= inv;
        s_feat[i] = v;
    }
    __syncthreads();

    const float4* brow = reinterpret_cast<const float4*>(bank + (size_t)q * D_);
    float acc[8];
    #pragma unroll
    for (int r = 0; r < 8; r++) acc[r] = 0.0f;

    #pragma unroll 4
    for (int c = 0; c < 128; c++) {
        float4 b = brow[c];
        #pragma unroll
        for (int r = 0; r < 8; r++) {
            float4 f = s_feat[r * 128 + c];   // broadcast across warp
            acc[r] += b.x * f.x + b.y * f.y + b.z * f.z + b.w * f.w;
        }
    }

    float ibn = g_bank_inv[q];
    #pragma unroll
    for (int r = 0; r < 8; r++)
        g_dist[(size_t)(r0 + r) * Q_ + q] = 1.0f - acc[r] * ibn;
}

// ---------------------------------------------------------------------------
// Kernel T: top-4 largest distances per row, lax.top_k tie semantics
// (value descending, index ascending). 4 masked block-argmax passes.
// ---------------------------------------------------------------------------
__global__ void topk_kernel() {
    __shared__ float s_d[Q_];
    __shared__ float s_v[256];
    __shared__ int   s_i[256];
    const int n = blockIdx.x, tid = threadIdx.x;

    for (int qq = tid; qq < Q_; qq += 256)
        s_d[qq] = g_dist[(size_t)n * Q_ + qq];
    __syncthreads();

    for (int k = 0; k < K_; k++) {
        float bv = -CUDART_INF_F; int bi = Q_;
        for (int qq = tid; qq < Q_; qq += 256) {
            float v = s_d[qq];
            if (v > bv) { bv = v; bi = qq; }  // ascending qq: strict > keeps lowest idx
        }
        s_v[tid] = bv; s_i[tid] = bi;
        __syncthreads();
        for (int s = 128; s > 0; s >>= 1) {
            if (tid < s) {
                float ov = s_v[tid + s]; int oi = s_i[tid + s];
                if (ov > s_v[tid] || (ov == s_v[tid] && oi < s_i[tid])) {
                    s_v[tid] = ov; s_i[tid] = oi;
                }
            }
            __syncthreads();
        }
        if (tid == 0) {
            g_topk[n * K_ + k] = s_i[0];
            s_d[s_i[0]] = -CUDART_INF_F;   // mask for next pass
        }
        __syncthreads();
    }
}

// ---------------------------------------------------------------------------
// Kernel C: grads mean (256x512), probs mean (256x1000) + argmax -> labels.
// One block per output row.
// ---------------------------------------------------------------------------
__global__ void small_gather_kernel(const float* __restrict__ bank,
                                    const float* __restrict__ probs,
                                    float* __restrict__ out) {
    const int n = blockIdx.x, tid = threadIdx.x;
    __shared__ int idx[K_];
    if (tid < K_) idx[tid] = g_topk[n * K_ + tid];
    __syncthreads();
    const int i0 = idx[0], i1 = idx[1], i2 = idx[2], i3 = idx[3];

    float* outg = out + OFF_GRADS + (size_t)n * D_;
    for (int d = tid; d < D_; d += 256)
        outg[d] = 0.25f * (bank[(size_t)i0 * D_ + d] + bank[(size_t)i1 * D_ + d] +
                           bank[(size_t)i2 * D_ + d] + bank[(size_t)i3 * D_ + d]);

    float* outp = out + OFF_PROBS + (size_t)n * C_;
    float bv = -CUDART_INF_F; int bc = C_;
    for (int c = tid; c < C_; c += 256) {
        float p = 0.25f * (probs[(size_t)i0 * C_ + c] + probs[(size_t)i1 * C_ + c] +
                           probs[(size_t)i2 * C_ + c] + probs[(size_t)i3 * C_ + c]);
        outp[c] = p;
        if (p > bv) { bv = p; bc = c; }   // ascending c within thread
    }
    __shared__ float s_v[256];
    __shared__ int   s_i[256];
    s_v[tid] = bv; s_i[tid] = bc;
    __syncthreads();
    for (int s = 128; s > 0; s >>= 1) {
        if (tid < s) {
            float ov = s_v[tid + s]; int oi = s_i[tid + s];
            if (ov > s_v[tid] || (ov == s_v[tid] && oi < s_i[tid])) {
                s_v[tid] = ov; s_i[tid] = oi;
            }
        }
        __syncthreads();
    }
    if (tid == 0) out[OFF_LABELS + n] = (float)s_i[0];
}

// ---------------------------------------------------------------------------
// Kernel D: image gather-mean — the HBM-bound bulk (770 MB streaming).
// Grid (147, 256): blockIdx.y = output row n, x*256+tid = float4 index.
// All threads in a block share the same 4 source rows -> perfectly coalesced.
// __ldcs/__stcs: streaming, avoid L2 pollution (no reuse).
// ---------------------------------------------------------------------------
__global__ void image_gather_kernel(const float* __restrict__ img,
                                    float* __restrict__ out) {
    const int n = blockIdx.y;
    const int j = blockIdx.x * blockDim.x + threadIdx.x;  // < IMG_/4 = 37632
    const int i0 = g_topk[n * K_ + 0];
    const int i1 = g_topk[n * K_ + 1];
    const int i2 = g_topk[n * K_ + 2];
    const int i3 = g_topk[n * K_ + 3];

    const float4* p0 = reinterpret_cast<const float4*>(img + (size_t)i0 * IMG_);
    const float4* p1 = reinterpret_cast<const float4*>(img + (size_t)i1 * IMG_);
    const float4* p2 = reinterpret_cast<const float4*>(img + (size_t)i2 * IMG_);
    const float4* p3 = reinterpret_cast<const float4*>(img + (size_t)i3 * IMG_);

    float4 a = __ldcs(p0 + j);
    float4 b = __ldcs(p1 + j);
    float4 c = __ldcs(p2 + j);
    float4 d = __ldcs(p3 + j);
    float4 r;
    r.x = 0.25f * (a.x + b.x + c.x + d.x);
    r.y = 0.25f * (a.y + b.y + c.y + d.y);
    r.z = 0.25f * (a.z + b.z + c.z + d.z);
    r.w = 0.25f * (a.w + b.w + c.w + d.w);
    float4* po = reinterpret_cast<float4*>(out + OFF_IMG + (size_t)n * IMG_);
    __stcs(po + j, r);
}

// ---------------------------------------------------------------------------
extern "C" void kernel_launch(void* const* d_in, const int* in_sizes, int n_in,
                              void* d_out, int out_size) {
    const float* feats = (const float*)d_in[0];   // (256, 512)
    const float* bank  = (const float*)d_in[1];   // (2048, 512)
    const float* probs = (const float*)d_in[2];   // (2048, 1000)
    const float* img   = (const float*)d_in[3];   // (2048, 3, 224, 224)
    float* out = (float*)d_out;

    norms_kernel<<<N_ + Q_, 128>>>(feats, bank);
    dim3 dg(Q_ / 256, N_ / 8);
    dist_kernel<<<dg, 256>>>(feats, bank);
    topk_kernel<<<N_, 256>>>();
    small_gather_kernel<<<N_, 256>>>(bank, probs, out);
    dim3 gi(IMG_ / 4 / 256, N_);
    image_gather_kernel<<<gi, 256>>>(img, out);
}

// round 3
// speedup vs baseline: 1.0373x; 1.0373x over previous
#include <cuda_runtime.h>
#include <math_constants.h>

#define N_    256
#define D_    512
#define Q_    2048
#define C_    1000
#define IMG_  150528   // 3*224*224
#define IMG4_ 37632    // IMG_/4
#define K_    4

// Output layout: labels | probs | images | grads (return order, float32)
#define OFF_LABELS 0
#define OFF_PROBS  (N_)
#define OFF_IMG    (N_ + N_*C_)
#define OFF_GRADS  (N_ + N_*C_ + N_*IMG_)

// Scratch (no cudaMalloc allowed; all usage is overwrite-based => deterministic)
__device__ float  g_bank_inv[Q_];
__device__ float  g_dist[N_ * Q_];
__device__ int    g_topk[N_ * K_];
__device__ float4 g_bankT[128 * Q_];   // bankT[cf4][q] : 4 MB, L2-resident

// packed f32x2 FMA (ptxas only emits FFMA2 via explicit PTX)
__device__ __forceinline__ void ffma2(unsigned long long& acc,
                                      unsigned long long a,
                                      unsigned long long b) {
    asm("fma.rn.f32x2 %0, %1, %2, %0;" : "+l"(acc) : "l"(a), "l"(b));
}
__device__ __forceinline__ float unpack_sum(unsigned long long v) {
    float lo = __uint_as_float((unsigned)(v & 0xffffffffull));
    float hi = __uint_as_float((unsigned)(v >> 32));
    return lo + hi;
}

// ---------------------------------------------------------------------------
// Kernel A: inverse L2 norms for the bank rows only (feature norms are
// computed inline in dist_kernel).
// ---------------------------------------------------------------------------
__global__ void norms_kernel(const float* __restrict__ bank) {
    int r = blockIdx.x;
    float4 v = reinterpret_cast<const float4*>(bank + (size_t)r * D_)[threadIdx.x];
    float ss = v.x * v.x + v.y * v.y + v.z * v.z + v.w * v.w;
    #pragma unroll
    for (int o = 16; o > 0; o >>= 1)
        ss += __shfl_xor_sync(0xffffffffu, ss, o);
    __shared__ float ws[4];
    if ((threadIdx.x & 31) == 0) ws[threadIdx.x >> 5] = ss;
    __syncthreads();
    if (threadIdx.x == 0) {
        float s = ws[0] + ws[1] + ws[2] + ws[3];
        g_bank_inv[r] = 1.0f / fmaxf(sqrtf(s), 1e-12f);
    }
}

// ---------------------------------------------------------------------------
// Kernel B0: transpose bank to bankT[cf4][q] (float4 granularity) so the
// dist kernel's bank loads are warp-coalesced (consecutive q per lane).
// ---------------------------------------------------------------------------
__global__ void transpose_kernel(const float4* __restrict__ bank4) {
    __shared__ float4 tile[32][33];
    const int tx = threadIdx.x & 31;         // cf4 within tile (load) / q (store)
    const int ty = threadIdx.x >> 5;         // 0..7
    const int qt = blockIdx.x * 32;
    const int ct = blockIdx.y * 32;
    #pragma unroll
    for (int i = 0; i < 4; i++)
        tile[ty + 8 * i][tx] = bank4[(size_t)(qt + ty + 8 * i) * 128 + ct + tx];
    __syncthreads();
    #pragma unroll
    for (int i = 0; i < 4; i++)
        g_bankT[(size_t)(ct + ty + 8 * i) * Q_ + qt + tx] = tile[tx][ty + 8 * i];
}

// ---------------------------------------------------------------------------
// Kernel B: distance matrix. Grid (4 q-chunks x 32 r-groups) = 128 blocks,
// 128 threads. Each thread owns 4 q's (qpt=4) x 8 feature rows.
// Bank loads from bankT are coalesced; feature rows broadcast from smem;
// FFMA2 packed math. Feature norms computed inline.
// ---------------------------------------------------------------------------
__global__ void __launch_bounds__(128) dist_kernel(const float4* __restrict__ feats4) {
    __shared__ float4 s_feat[8 * 128];   // 8 rows x 512 floats
    __shared__ float  s_inv[8];
    const int tid = threadIdx.x;
    const int r0  = blockIdx.y * 8;
    const int qb  = blockIdx.x * 512;

    #pragma unroll
    for (int i = tid; i < 8 * 128; i += 128)
        s_feat[i] = feats4[(size_t)r0 * 128 + i];
    __syncthreads();

    // inline feature norms: warp w reduces rows 2w and 2w+1
    {
        const int w = tid >> 5, lane = tid & 31;
        #pragma unroll
        for (int rr = 2 * w; rr < 2 * w + 2; rr++) {
            float ss = 0.0f;
            #pragma unroll
            for (int c = lane; c < 128; c += 32) {
                float4 v = s_feat[rr * 128 + c];
                ss += v.x * v.x + v.y * v.y + v.z * v.z + v.w * v.w;
            }
            #pragma unroll
            for (int o = 16; o > 0; o >>= 1)
                ss += __shfl_xor_sync(0xffffffffu, ss, o);
            if (lane == 0) s_inv[rr] = 1.0f / fmaxf(sqrtf(ss), 1e-12f);
        }
    }
    __syncthreads();

    unsigned long long acc[8][4];
    #pragma unroll
    for (int r = 0; r < 8; r++)
        #pragma unroll
        for (int j = 0; j < 4; j++) acc[r][j] = 0ull;

    const ulonglong2* bT = reinterpret_cast<const ulonglong2*>(g_bankT);
    const ulonglong2* sf = reinterpret_cast<const ulonglong2*>(s_feat);

    #pragma unroll 2
    for (int c = 0; c < 128; c++) {
        const ulonglong2* row = bT + (size_t)c * Q_ + qb + tid;
        ulonglong2 b0 = row[0];
        ulonglong2 b1 = row[128];
        ulonglong2 b2 = row[256];
        ulonglong2 b3 = row[384];
        #pragma unroll
        for (int r = 0; r < 8; r++) {
            ulonglong2 f = sf[r * 128 + c];
            ffma2(acc[r][0], f.x, b0.x); ffma2(acc[r][0], f.y, b0.y);
            ffma2(acc[r][1], f.x, b1.x); ffma2(acc[r][1], f.y, b1.y);
            ffma2(acc[r][2], f.x, b2.x); ffma2(acc[r][2], f.y, b2.y);
            ffma2(acc[r][3], f.x, b3.x); ffma2(acc[r][3], f.y, b3.y);
        }
    }

    #pragma unroll
    for (int j = 0; j < 4; j++) {
        const int q = qb + tid + 128 * j;
        const float ibn = g_bank_inv[q];
        #pragma unroll
        for (int r = 0; r < 8; r++) {
            float dot = unpack_sum(acc[r][j]);
            g_dist[(size_t)(r0 + r) * Q_ + q] = 1.0f - dot * s_inv[r] * ibn;
        }
    }
}

// ---------------------------------------------------------------------------
// Kernel T: fused top-4 (lax.top_k tie semantics: value desc, index asc)
// + grads/probs gather-mean + argmax labels. One block per feature row.
// ---------------------------------------------------------------------------
__global__ void topk_gather_kernel(const float* __restrict__ bank,
                                   const float* __restrict__ probs,
                                   float* __restrict__ out) {
    __shared__ float s_d[Q_];
    __shared__ float s_v[256];
    __shared__ int   s_i[256];
    __shared__ int   s_idx[K_];
    const int n = blockIdx.x, tid = threadIdx.x;

    for (int qq = tid; qq < Q_; qq += 256)
        s_d[qq] = g_dist[(size_t)n * Q_ + qq];
    __syncthreads();

    for (int k = 0; k < K_; k++) {
        float bv = -CUDART_INF_F; int bi = Q_;
        for (int qq = tid; qq < Q_; qq += 256) {
            float v = s_d[qq];
            if (v > bv) { bv = v; bi = qq; }   // ascending qq: strict > keeps lowest idx
        }
        s_v[tid] = bv; s_i[tid] = bi;
        __syncthreads();
        for (int s = 128; s > 0; s >>= 1) {
            if (tid < s) {
                float ov = s_v[tid + s]; int oi = s_i[tid + s];
                if (ov > s_v[tid] || (ov == s_v[tid] && oi < s_i[tid])) {
                    s_v[tid] = ov; s_i[tid] = oi;
                }
            }
            __syncthreads();
        }
        if (tid == 0) {
            s_idx[k] = s_i[0];
            g_topk[n * K_ + k] = s_i[0];
            s_d[s_i[0]] = -CUDART_INF_F;       // mask for next pass
        }
        __syncthreads();
    }

    const int i0 = s_idx[0], i1 = s_idx[1], i2 = s_idx[2], i3 = s_idx[3];

    float* outg = out + OFF_GRADS + (size_t)n * D_;
    for (int d = tid; d < D_; d += 256)
        outg[d] = 0.25f * (bank[(size_t)i0 * D_ + d] + bank[(size_t)i1 * D_ + d] +
                           bank[(size_t)i2 * D_ + d] + bank[(size_t)i3 * D_ + d]);

    float* outp = out + OFF_PROBS + (size_t)n * C_;
    float bv = -CUDART_INF_F; int bc = C_;
    for (int c = tid; c < C_; c += 256) {
        float p = 0.25f * (probs[(size_t)i0 * C_ + c] + probs[(size_t)i1 * C_ + c] +
                           probs[(size_t)i2 * C_ + c] + probs[(size_t)i3 * C_ + c]);
        outp[c] = p;
        if (p > bv) { bv = p; bc = c; }
    }
    s_v[tid] = bv; s_i[tid] = bc;
    __syncthreads();
    for (int s = 128; s > 0; s >>= 1) {
        if (tid < s) {
            float ov = s_v[tid + s]; int oi = s_i[tid + s];
            if (ov > s_v[tid] || (ov == s_v[tid] && oi < s_i[tid])) {
                s_v[tid] = ov; s_i[tid] = oi;
            }
        }
        __syncthreads();
    }
    if (tid == 0) out[OFF_LABELS + n] = (float)s_i[0];
}

// ---------------------------------------------------------------------------
// Kernel D: image gather-mean. Grid (n=256 FAST, chunk=21 SLOW): all 256
// output rows process the same column chunk concurrently, so duplicate
// neighbor indices across rows (~20% expected) hit in L2. Default-cached
// loads, streaming stores. 1792 float4 per (n, chunk), 7 unrolled iters.
// ---------------------------------------------------------------------------
__global__ void image_gather_kernel(const float4* __restrict__ img4,
                                    float* __restrict__ out) {
    const int n    = blockIdx.x;
    const int base = blockIdx.y * 1792 + threadIdx.x;   // 21 chunks * 1792 = 37632
    const int i0 = g_topk[n * K_ + 0];
    const int i1 = g_topk[n * K_ + 1];
    const int i2 = g_topk[n * K_ + 2];
    const int i3 = g_topk[n * K_ + 3];

    const float4* p0 = img4 + (size_t)i0 * IMG4_;
    const float4* p1 = img4 + (size_t)i1 * IMG4_;
    const float4* p2 = img4 + (size_t)i2 * IMG4_;
    const float4* p3 = img4 + (size_t)i3 * IMG4_;
    float4* po = reinterpret_cast<float4*>(out + OFF_IMG) + (size_t)n * IMG4_;

    #pragma unroll
    for (int t = 0; t < 7; t++) {
        const int j = base + t * 256;
        float4 a = p0[j];
        float4 b = p1[j];
        float4 c = p2[j];
        float4 d = p3[j];
        float4 r;
        r.x = 0.25f * (a.x + b.x + c.x + d.x);
        r.y = 0.25f * (a.y + b.y + c.y + d.y);
        r.z = 0.25f * (a.z + b.z + c.z + d.z);
        r.w = 0.25f * (a.w + b.w + c.w + d.w);
        __stcs(po + j, r);
    }
}

// ---------------------------------------------------------------------------
extern "C" void kernel_launch(void* const* d_in, const int* in_sizes, int n_in,
                              void* d_out, int out_size) {
    const float* feats = (const float*)d_in[0];   // (256, 512)
    const float* bank  = (const float*)d_in[1];   // (2048, 512)
    const float* probs = (const float*)d_in[2];   // (2048, 1000)
    const float* img   = (const float*)d_in[3];   // (2048, 3, 224, 224)
    float* out = (float*)d_out;

    norms_kernel<<<Q_, 128>>>(bank);
    transpose_kernel<<<dim3(Q_ / 32, 128 / 32), 256>>>(
        reinterpret_cast<const float4*>(bank));
    dist_kernel<<<dim3(4, N_ / 8), 128>>>(
        reinterpret_cast<const float4*>(feats));
    topk_gather_kernel<<<N_, 256>>>(bank, probs, out);
    image_gather_kernel<<<dim3(N_, 21), 256>>>(
        reinterpret_cast<const float4*>(img), out);
}

// round 4
// speedup vs baseline: 1.2510x; 1.2060x over previous
#include <cuda_runtime.h>
#include <math_constants.h>

#define N_    256
#define D_    512
#define Q_    2048
#define C_    1000
#define IMG_  150528   // 3*224*224
#define IMG4_ 37632    // IMG_/4 = 21 * 1792
#define K_    4

// Output layout: labels | probs | images | grads (return order, float32)
#define OFF_LABELS 0
#define OFF_PROBS  (N_)
#define OFF_IMG    (N_ + N_*C_)
#define OFF_GRADS  (N_ + N_*C_ + N_*IMG_)

// Scratch (no cudaMalloc allowed; all usage is overwrite-based => deterministic)
__device__ float  g_dist[N_ * Q_];
__device__ int    g_topk[N_ * K_];
__device__ float4 g_bankT[128 * Q_];   // bankT[cf4][q] : 4 MB, L2-resident

// packed f32x2 FMA (ptxas only emits FFMA2 via explicit PTX)
__device__ __forceinline__ void ffma2(unsigned long long& acc,
                                      unsigned long long a,
                                      unsigned long long b) {
    asm("fma.rn.f32x2 %0, %1, %2, %0;" : "+l"(acc) : "l"(a), "l"(b));
}
__device__ __forceinline__ float unpack_sum(unsigned long long v) {
    float lo = __uint_as_float((unsigned)(v & 0xffffffffull));
    float hi = __uint_as_float((unsigned)(v >> 32));
    return lo + hi;
}

// ---------------------------------------------------------------------------
// Kernel B0: transpose bank to bankT[cf4][q] (float4 granularity) so the
// dist kernel's bank loads are warp-coalesced (consecutive q per lane).
// ---------------------------------------------------------------------------
__global__ void transpose_kernel(const float4* __restrict__ bank4) {
    __shared__ float4 tile[32][33];
    const int tx = threadIdx.x & 31;
    const int ty = threadIdx.x >> 5;
    const int qt = blockIdx.x * 32;
    const int ct = blockIdx.y * 32;
    #pragma unroll
    for (int i = 0; i < 4; i++)
        tile[ty + 8 * i][tx] = bank4[(size_t)(qt + ty + 8 * i) * 128 + ct + tx];
    __syncthreads();
    #pragma unroll
    for (int i = 0; i < 4; i++)
        g_bankT[(size_t)(ct + ty + 8 * i) * Q_ + qt + tx] = tile[tx][ty + 8 * i];
}

// ---------------------------------------------------------------------------
// Kernel B: distance matrix. Grid (4 q-chunks x 32 r-groups), 128 threads.
// Thread tile: 8 feature rows x 4 q's. Bank self-dots (norms) computed
// inline, feature norms inline -> no separate norms kernel.
// ---------------------------------------------------------------------------
__global__ void __launch_bounds__(128) dist_kernel(const float4* __restrict__ feats4) {
    __shared__ float4 s_feat[8 * 128];   // 8 rows x 512 floats
    __shared__ float  s_inv[8];
    const int tid = threadIdx.x;
    const int r0  = blockIdx.y * 8;
    const int qb  = blockIdx.x * 512;

    #pragma unroll
    for (int i = tid; i < 8 * 128; i += 128)
        s_feat[i] = feats4[(size_t)r0 * 128 + i];
    __syncthreads();

    // inline feature norms: warp w reduces rows 2w and 2w+1
    {
        const int w = tid >> 5, lane = tid & 31;
        #pragma unroll
        for (int rr = 2 * w; rr < 2 * w + 2; rr++) {
            float ss = 0.0f;
            #pragma unroll
            for (int c = lane; c < 128; c += 32) {
                float4 v = s_feat[rr * 128 + c];
                ss += v.x * v.x + v.y * v.y + v.z * v.z + v.w * v.w;
            }
            #pragma unroll
            for (int o = 16; o > 0; o >>= 1)
                ss += __shfl_xor_sync(0xffffffffu, ss, o);
            if (lane == 0) s_inv[rr] = 1.0f / fmaxf(sqrtf(ss), 1e-12f);
        }
    }
    __syncthreads();

    unsigned long long acc[8][4];
    unsigned long long bb[4];
    #pragma unroll
    for (int r = 0; r < 8; r++)
        #pragma unroll
        for (int j = 0; j < 4; j++) acc[r][j] = 0ull;
    #pragma unroll
    for (int j = 0; j < 4; j++) bb[j] = 0ull;

    const ulonglong2* bT = reinterpret_cast<const ulonglong2*>(g_bankT);
    const ulonglong2* sf = reinterpret_cast<const ulonglong2*>(s_feat);

    #pragma unroll 2
    for (int c = 0; c < 128; c++) {
        const ulonglong2* row = bT + (size_t)c * Q_ + qb + tid;
        ulonglong2 b0 = row[0];
        ulonglong2 b1 = row[128];
        ulonglong2 b2 = row[256];
        ulonglong2 b3 = row[384];
        // bank self-dots (inline norms)
        ffma2(bb[0], b0.x, b0.x); ffma2(bb[0], b0.y, b0.y);
        ffma2(bb[1], b1.x, b1.x); ffma2(bb[1], b1.y, b1.y);
        ffma2(bb[2], b2.x, b2.x); ffma2(bb[2], b2.y, b2.y);
        ffma2(bb[3], b3.x, b3.x); ffma2(bb[3], b3.y, b3.y);
        #pragma unroll
        for (int r = 0; r < 8; r++) {
            ulonglong2 f = sf[r * 128 + c];
            ffma2(acc[r][0], f.x, b0.x); ffma2(acc[r][0], f.y, b0.y);
            ffma2(acc[r][1], f.x, b1.x); ffma2(acc[r][1], f.y, b1.y);
            ffma2(acc[r][2], f.x, b2.x); ffma2(acc[r][2], f.y, b2.y);
            ffma2(acc[r][3], f.x, b3.x); ffma2(acc[r][3], f.y, b3.y);
        }
    }

    #pragma unroll
    for (int j = 0; j < 4; j++) {
        const int q = qb + tid + 128 * j;
        const float ibn = 1.0f / fmaxf(sqrtf(unpack_sum(bb[j])), 1e-12f);
        #pragma unroll
        for (int r = 0; r < 8; r++) {
            float dot = unpack_sum(acc[r][j]);
            g_dist[(size_t)(r0 + r) * Q_ + q] = 1.0f - dot * s_inv[r] * ibn;
        }
    }
}

// ---------------------------------------------------------------------------
// Kernel T: top-4 indices only (lax.top_k tie semantics: value desc, index
// asc). Warp-shfl argmax passes: 2 syncs per pass instead of 9.
// ---------------------------------------------------------------------------
__global__ void topk_kernel() {
    __shared__ float s_d[Q_];
    __shared__ float s_wv[8];
    __shared__ int   s_wi[8];
    const int n = blockIdx.x, tid = threadIdx.x;
    const int lane = tid & 31, w = tid >> 5;

    for (int qq = tid; qq < Q_; qq += 256)
        s_d[qq] = g_dist[(size_t)n * Q_ + qq];
    __syncthreads();

    for (int k = 0; k < K_; k++) {
        float bv = -CUDART_INF_F; int bi = Q_;
        #pragma unroll
        for (int t = 0; t < 8; t++) {
            int qq = tid + t * 256;                 // ascending per thread
            float v = s_d[qq];
            if (v > bv) { bv = v; bi = qq; }        // strict > keeps lowest idx
        }
        #pragma unroll
        for (int o = 16; o > 0; o >>= 1) {
            float ov = __shfl_xor_sync(0xffffffffu, bv, o);
            int   oi = __shfl_xor_sync(0xffffffffu, bi, o);
            if (ov > bv || (ov == bv && oi < bi)) { bv = ov; bi = oi; }
        }
        if (lane == 0) { s_wv[w] = bv; s_wi[w] = bi; }
        __syncthreads();
        if (w == 0) {
            float v2 = (lane < 8) ? s_wv[lane] : -CUDART_INF_F;
            int   i2 = (lane < 8) ? s_wi[lane] : Q_;
            #pragma unroll
            for (int o = 4; o > 0; o >>= 1) {
                float ov = __shfl_xor_sync(0xffffffffu, v2, o);
                int   oi = __shfl_xor_sync(0xffffffffu, i2, o);
                if (ov > v2 || (ov == v2 && oi < i2)) { v2 = ov; i2 = oi; }
            }
            if (lane == 0) {
                g_topk[n * K_ + k] = i2;
                s_d[i2] = -CUDART_INF_F;            // mask for next pass
            }
        }
        __syncthreads();
    }
}

// ---------------------------------------------------------------------------
// Kernel D (fused): grid (256, 22).
//   blockIdx.y < 21 : image gather-mean chunk (1792 float4). n is the FAST
//                     grid dim so all rows stream the same column chunk
//                     concurrently -> duplicate neighbor rows hit L2.
//   blockIdx.y == 21: probs mean + argmax label + grads mean for row n.
// The 256 small blocks hide entirely under the ~5376 image blocks.
// ---------------------------------------------------------------------------
__global__ void fused_gather_kernel(const float4* __restrict__ img4,
                                    const float* __restrict__ bank,
                                    const float* __restrict__ probs,
                                    float* __restrict__ out) {
    const int n = blockIdx.x, tid = threadIdx.x;
    const int4 ii = *reinterpret_cast<const int4*>(&g_topk[n * K_]);
    const int i0 = ii.x, i1 = ii.y, i2 = ii.z, i3 = ii.w;

    if (blockIdx.y < 21) {
        const int base = blockIdx.y * 1792 + tid;
        const float4* p0 = img4 + (size_t)i0 * IMG4_;
        const float4* p1 = img4 + (size_t)i1 * IMG4_;
        const float4* p2 = img4 + (size_t)i2 * IMG4_;
        const float4* p3 = img4 + (size_t)i3 * IMG4_;
        float4* po = reinterpret_cast<float4*>(out + OFF_IMG) + (size_t)n * IMG4_;
        #pragma unroll
        for (int t = 0; t < 7; t++) {
            const int j = base + t * 256;
            float4 a = p0[j];
            float4 b = p1[j];
            float4 c = p2[j];
            float4 d = p3[j];
            float4 r;
            r.x = 0.25f * (a.x + b.x + c.x + d.x);
            r.y = 0.25f * (a.y + b.y + c.y + d.y);
            r.z = 0.25f * (a.z + b.z + c.z + d.z);
            r.w = 0.25f * (a.w + b.w + c.w + d.w);
            __stcs(po + j, r);
        }
    } else {
        // grads mean (512)
        float* outg = out + OFF_GRADS + (size_t)n * D_;
        for (int d = tid; d < D_; d += 256)
            outg[d] = 0.25f * (bank[(size_t)i0 * D_ + d] + bank[(size_t)i1 * D_ + d] +
                               bank[(size_t)i2 * D_ + d] + bank[(size_t)i3 * D_ + d]);
        // probs mean (1000) + argmax -> label
        float* outp = out + OFF_PROBS + (size_t)n * C_;
        float bv = -CUDART_INF_F; int bc = C_;
        for (int c = tid; c < C_; c += 256) {
            float p = 0.25f * (probs[(size_t)i0 * C_ + c] + probs[(size_t)i1 * C_ + c] +
                               probs[(size_t)i2 * C_ + c] + probs[(size_t)i3 * C_ + c]);
            outp[c] = p;
            if (p > bv) { bv = p; bc = c; }          // ascending c per thread
        }
        const int lane = tid & 31, w = tid >> 5;
        __shared__ float s_wv[8];
        __shared__ int   s_wi[8];
        #pragma unroll
        for (int o = 16; o > 0; o >>= 1) {
            float ov = __shfl_xor_sync(0xffffffffu, bv, o);
            int   oi = __shfl_xor_sync(0xffffffffu, bc, o);
            if (ov > bv || (ov == bv && oi < bc)) { bv = ov; bc = oi; }
        }
        if (lane == 0) { s_wv[w] = bv; s_wi[w] = bc; }
        __syncthreads();
        if (tid == 0) {
            float v2 = s_wv[0]; int i2b = s_wi[0];
            #pragma unroll
            for (int q = 1; q < 8; q++) {
                if (s_wv[q] > v2 || (s_wv[q] == v2 && s_wi[q] < i2b)) {
                    v2 = s_wv[q]; i2b = s_wi[q];
                }
            }
            out[OFF_LABELS + n] = (float)i2b;
        }
    }
}

// ---------------------------------------------------------------------------
extern "C" void kernel_launch(void* const* d_in, const int* in_sizes, int n_in,
                              void* d_out, int out_size) {
    const float* feats = (const float*)d_in[0];   // (256, 512)
    const float* bank  = (const float*)d_in[1];   // (2048, 512)
    const float* probs = (const float*)d_in[2];   // (2048, 1000)
    const float* img   = (const float*)d_in[3];   // (2048, 3, 224, 224)
    float* out = (float*)d_out;

    transpose_kernel<<<dim3(Q_ / 32, 128 / 32), 256>>>(
        reinterpret_cast<const float4*>(bank));
    dist_kernel<<<dim3(4, N_ / 8), 128>>>(
        reinterpret_cast<const float4*>(feats));
    topk_kernel<<<N_, 256>>>();
    fused_gather_kernel<<<dim3(N_, 22), 256>>>(
        reinterpret_cast<const float4*>(img), bank, probs, out);
}

// round 5
// speedup vs baseline: 1.2541x; 1.0025x over previous
#include <cuda_runtime.h>
#include <math_constants.h>

#define N_    256
#define D_    512
#define Q_    2048
#define C_    1000
#define IMG_  150528   // 3*224*224
#define IMG4_ 37632    // IMG_/4 = 21 * 1792
#define K_    4

// Output layout: labels | probs | images | grads (return order, float32)
#define OFF_LABELS 0
#define OFF_PROBS  (N_)
#define OFF_IMG    (N_ + N_*C_)
#define OFF_GRADS  (N_ + N_*C_ + N_*IMG_)

// Scratch (no cudaMalloc allowed; overwrite-based => deterministic)
__device__ float  g_dist[N_ * Q_];
__device__ int    g_topk[N_ * K_];
__device__ float4 g_bankT[128 * Q_];   // bankT[cf4][q] : 4 MB, L2-resident

// packed f32x2 FMA (ptxas only emits FFMA2 via explicit PTX)
__device__ __forceinline__ void ffma2(unsigned long long& acc,
                                      unsigned long long a,
                                      unsigned long long b) {
    asm("fma.rn.f32x2 %0, %1, %2, %0;" : "+l"(acc) : "l"(a), "l"(b));
}
__device__ __forceinline__ float unpack_sum(unsigned long long v) {
    float lo = __uint_as_float((unsigned)(v & 0xffffffffull));
    float hi = __uint_as_float((unsigned)(v >> 32));
    return lo + hi;
}

// ---------------------------------------------------------------------------
// Kernel B0: transpose bank to bankT[cf4][q] (float4 granularity) so the
// dist kernel's bank loads are warp-coalesced (consecutive q per lane).
// ---------------------------------------------------------------------------
__global__ void transpose_kernel(const float4* __restrict__ bank4) {
    __shared__ float4 tile[32][33];
    const int tx = threadIdx.x & 31;
    const int ty = threadIdx.x >> 5;
    const int qt = blockIdx.x * 32;
    const int ct = blockIdx.y * 32;
    #pragma unroll
    for (int i = 0; i < 4; i++)
        tile[ty + 8 * i][tx] = bank4[(size_t)(qt + ty + 8 * i) * 128 + ct + tx];
    __syncthreads();
    #pragma unroll
    for (int i = 0; i < 4; i++)
        g_bankT[(size_t)(ct + ty + 8 * i) * Q_ + qt + tx] = tile[tx][ty + 8 * i];
}

// ---------------------------------------------------------------------------
// Kernel B: distance matrix. Grid (8 q-chunks x 16 r-groups) = 128 blocks,
// 256 threads (8 warps -> 2/SMSP for L2-latency hiding). Thread tile:
// 16 feature rows x 1 q. Bank L2 traffic = 16 x 4MB = 64 MB.
// Bank self-dots (norms) and feature norms computed inline.
// ---------------------------------------------------------------------------
__global__ void __launch_bounds__(256) dist_kernel(const float4* __restrict__ feats4) {
    __shared__ float4 s_feat[16 * 128];   // 16 rows x 512 floats = 32 KB
    __shared__ float  s_inv[16];
    const int tid = threadIdx.x;
    const int r0  = blockIdx.y * 16;
    const int qb  = blockIdx.x * 256;

    #pragma unroll
    for (int i = tid; i < 16 * 128; i += 256)
        s_feat[i] = feats4[(size_t)r0 * 128 + i];
    __syncthreads();

    // inline feature norms: warp w reduces rows 2w and 2w+1
    {
        const int w = tid >> 5, lane = tid & 31;
        #pragma unroll
        for (int rr = 2 * w; rr < 2 * w + 2; rr++) {
            float ss = 0.0f;
            #pragma unroll
            for (int c = lane; c < 128; c += 32) {
                float4 v = s_feat[rr * 128 + c];
                ss += v.x * v.x + v.y * v.y + v.z * v.z + v.w * v.w;
            }
            #pragma unroll
            for (int o = 16; o > 0; o >>= 1)
                ss += __shfl_xor_sync(0xffffffffu, ss, o);
            if (lane == 0) s_inv[rr] = 1.0f / fmaxf(sqrtf(ss), 1e-12f);
        }
    }
    __syncthreads();

    unsigned long long acc[16];
    unsigned long long bb = 0ull;
    #pragma unroll
    for (int r = 0; r < 16; r++) acc[r] = 0ull;

    const ulonglong2* bT = reinterpret_cast<const ulonglong2*>(g_bankT) + qb + tid;
    const ulonglong2* sf = reinterpret_cast<const ulonglong2*>(s_feat);

    #pragma unroll 4
    for (int c = 0; c < 128; c++) {
        ulonglong2 b = bT[(size_t)c * Q_];
        ffma2(bb, b.x, b.x);
        ffma2(bb, b.y, b.y);
        #pragma unroll
        for (int r = 0; r < 16; r++) {
            ulonglong2 f = sf[r * 128 + c];       // warp-broadcast
            ffma2(acc[r], f.x, b.x);
            ffma2(acc[r], f.y, b.y);
        }
    }

    const int q = qb + tid;
    const float ibn = 1.0f / fmaxf(sqrtf(unpack_sum(bb)), 1e-12f);
    #pragma unroll
    for (int r = 0; r < 16; r++) {
        float dot = unpack_sum(acc[r]);
        g_dist[(size_t)(r0 + r) * Q_ + q] = 1.0f - dot * s_inv[r] * ibn;
    }
}

// ---------------------------------------------------------------------------
// Kernel T: top-4 indices only (lax.top_k tie semantics: value desc, index
// asc). Warp-shfl argmax passes: 2 syncs per pass.
// ---------------------------------------------------------------------------
__global__ void topk_kernel() {
    __shared__ float s_d[Q_];
    __shared__ float s_wv[8];
    __shared__ int   s_wi[8];
    const int n = blockIdx.x, tid = threadIdx.x;
    const int lane = tid & 31, w = tid >> 5;

    for (int qq = tid; qq < Q_; qq += 256)
        s_d[qq] = g_dist[(size_t)n * Q_ + qq];
    __syncthreads();

    for (int k = 0; k < K_; k++) {
        float bv = -CUDART_INF_F; int bi = Q_;
        #pragma unroll
        for (int t = 0; t < 8; t++) {
            int qq = tid + t * 256;                 // ascending per thread
            float v = s_d[qq];
            if (v > bv) { bv = v; bi = qq; }        // strict > keeps lowest idx
        }
        #pragma unroll
        for (int o = 16; o > 0; o >>= 1) {
            float ov = __shfl_xor_sync(0xffffffffu, bv, o);
            int   oi = __shfl_xor_sync(0xffffffffu, bi, o);
            if (ov > bv || (ov == bv && oi < bi)) { bv = ov; bi = oi; }
        }
        if (lane == 0) { s_wv[w] = bv; s_wi[w] = bi; }
        __syncthreads();
        if (w == 0) {
            float v2 = (lane < 8) ? s_wv[lane] : -CUDART_INF_F;
            int   i2 = (lane < 8) ? s_wi[lane] : Q_;
            #pragma unroll
            for (int o = 4; o > 0; o >>= 1) {
                float ov = __shfl_xor_sync(0xffffffffu, v2, o);
                int   oi = __shfl_xor_sync(0xffffffffu, i2, o);
                if (ov > v2 || (ov == v2 && oi < i2)) { v2 = ov; i2 = oi; }
            }
            if (lane == 0) {
                g_topk[n * K_ + k] = i2;
                s_d[i2] = -CUDART_INF_F;            // mask for next pass
            }
        }
        __syncthreads();
    }
}

// ---------------------------------------------------------------------------
// Kernel D (fused): grid (256, 22).
//   blockIdx.y < 21 : image gather-mean chunk (1792 float4). n is the FAST
//                     grid dim so all rows stream the same column chunk
//                     concurrently -> duplicate neighbor rows hit L2.
//   blockIdx.y == 21: probs mean + argmax label + grads mean for row n.
// ---------------------------------------------------------------------------
__global__ void fused_gather_kernel(const float4* __restrict__ img4,
                                    const float* __restrict__ bank,
                                    const float* __restrict__ probs,
                                    float* __restrict__ out) {
    const int n = blockIdx.x, tid = threadIdx.x;
    const int4 ii = *reinterpret_cast<const int4*>(&g_topk[n * K_]);
    const int i0 = ii.x, i1 = ii.y, i2 = ii.z, i3 = ii.w;

    if (blockIdx.y < 21) {
        const int base = blockIdx.y * 1792 + tid;
        const float4* p0 = img4 + (size_t)i0 * IMG4_;
        const float4* p1 = img4 + (size_t)i1 * IMG4_;
        const float4* p2 = img4 + (size_t)i2 * IMG4_;
        const float4* p3 = img4 + (size_t)i3 * IMG4_;
        float4* po = reinterpret_cast<float4*>(out + OFF_IMG) + (size_t)n * IMG4_;
        #pragma unroll
        for (int t = 0; t < 7; t++) {
            const int j = base + t * 256;
            float4 a = p0[j];
            float4 b = p1[j];
            float4 c = p2[j];
            float4 d = p3[j];
            float4 r;
            r.x = 0.25f * (a.x + b.x + c.x + d.x);
            r.y = 0.25f * (a.y + b.y + c.y + d.y);
            r.z = 0.25f * (a.z + b.z + c.z + d.z);
            r.w = 0.25f * (a.w + b.w + c.w + d.w);
            __stcs(po + j, r);
        }
    } else {
        // grads mean (512)
        float* outg = out + OFF_GRADS + (size_t)n * D_;
        for (int d = tid; d < D_; d += 256)
            outg[d] = 0.25f * (bank[(size_t)i0 * D_ + d] + bank[(size_t)i1 * D_ + d] +
                               bank[(size_t)i2 * D_ + d] + bank[(size_t)i3 * D_ + d]);
        // probs mean (1000) + argmax -> label
        float* outp = out + OFF_PROBS + (size_t)n * C_;
        float bv = -CUDART_INF_F; int bc = C_;
        for (int c = tid; c < C_; c += 256) {
            float p = 0.25f * (probs[(size_t)i0 * C_ + c] + probs[(size_t)i1 * C_ + c] +
                               probs[(size_t)i2 * C_ + c] + probs[(size_t)i3 * C_ + c]);
            outp[c] = p;
            if (p > bv) { bv = p; bc = c; }          // ascending c per thread
        }
        const int lane = tid & 31, w = tid >> 5;
        __shared__ float s_wv[8];
        __shared__ int   s_wi[8];
        #pragma unroll
        for (int o = 16; o > 0; o >>= 1) {
            float ov = __shfl_xor_sync(0xffffffffu, bv, o);
            int   oi = __shfl_xor_sync(0xffffffffu, bc, o);
            if (ov > bv || (ov == bv && oi < bc)) { bv = ov; bc = oi; }
        }
        if (lane == 0) { s_wv[w] = bv; s_wi[w] = bc; }
        __syncthreads();
        if (tid == 0) {
            float v2 = s_wv[0]; int i2b = s_wi[0];
            #pragma unroll
            for (int q = 1; q < 8; q++) {
                if (s_wv[q] > v2 || (s_wv[q] == v2 && s_wi[q] < i2b)) {
                    v2 = s_wv[q]; i2b = s_wi[q];
                }
            }
            out[OFF_LABELS + n] = (float)i2b;
        }
    }
}

// ---------------------------------------------------------------------------
extern "C" void kernel_launch(void* const* d_in, const int* in_sizes, int n_in,
                              void* d_out, int out_size) {
    const float* feats = (const float*)d_in[0];   // (256, 512)
    const float* bank  = (const float*)d_in[1];   // (2048, 512)
    const float* probs = (const float*)d_in[2];   // (2048, 1000)
    const float* img   = (const float*)d_in[3];   // (2048, 3, 224, 224)
    float* out = (float*)d_out;

    transpose_kernel<<<dim3(Q_ / 32, 128 / 32), 256>>>(
        reinterpret_cast<const float4*>(bank));
    dist_kernel<<<dim3(Q_ / 256, N_ / 16), 256>>>(
        reinterpret_cast<const float4*>(feats));
    topk_kernel<<<N_, 256>>>();
    fused_gather_kernel<<<dim3(N_, 22), 256>>>(
        reinterpret_cast<const float4*>(img), bank, probs, out);
}